// round 1
// baseline (speedup 1.0000x reference)
#include <cuda_runtime.h>

#define NN 50000
#define HD 128
#define EE 640000
#define GG 128

// Scratch ping-pong buffers (25.6 MB each)
__device__ float g_bufA[NN * HD];
__device__ float g_bufB[NN * HD];
__device__ float g_bufC[NN * HD];

// ---------------------------------------------------------------------------
// GEMM: out[M,128] = epi(A[M,128] @ W[128,128] + bias)
// epi = relu, then optional BN ((v-mm)*g*rsqrt(mv+eps)+be). Optional dual write.
// Tile: 64 rows x 128 cols per 256-thread block; thread tile 4x8; BK=32.
// ---------------------------------------------------------------------------
template <bool DO_BN, bool DUAL>
__global__ void __launch_bounds__(256, 4) gemm128(
    const float* __restrict__ A, const float* __restrict__ W,
    const float* __restrict__ bias,
    const float* __restrict__ gam, const float* __restrict__ bet,
    const float* __restrict__ mmean, const float* __restrict__ mvar,
    float* __restrict__ out, float* __restrict__ out2, int M)
{
    __shared__ float As[32][65];    // [k][row], padded: conflict-free
    __shared__ float Ws[32][128];   // [k][col]

    const int tid = threadIdx.x;
    const int tx = tid & 15;        // col group (8 cols each)
    const int ty = tid >> 4;        // row group (4 rows each)
    const int row0 = blockIdx.x * 64;

    float acc[4][8];
#pragma unroll
    for (int i = 0; i < 4; i++)
#pragma unroll
        for (int j = 0; j < 8; j++) acc[i][j] = 0.f;

#pragma unroll 1
    for (int kt = 0; kt < 4; ++kt) {
        // Load A tile: 64 rows x 32 k (2 float4 per thread, coalesced)
#pragma unroll
        for (int i = 0; i < 2; i++) {
            int idx = tid + i * 256;        // 0..511 float4 slots
            int r = idx >> 3;               // 0..63
            int kq = idx & 7;               // float4 within 32-k chunk
            int grow = row0 + r;
            float4 v = make_float4(0.f, 0.f, 0.f, 0.f);
            if (grow < M)
                v = *(const float4*)(A + grow * HD + kt * 32 + kq * 4);
            As[kq * 4 + 0][r] = v.x;
            As[kq * 4 + 1][r] = v.y;
            As[kq * 4 + 2][r] = v.z;
            As[kq * 4 + 3][r] = v.w;
        }
        // Load W tile: 32 k x 128 cols (4 float4 per thread, coalesced)
#pragma unroll
        for (int i = 0; i < 4; i++) {
            int idx = tid + i * 256;        // 0..1023 float4 slots
            int kr = idx >> 5;              // 0..31
            int c4 = idx & 31;
            float4 v = *(const float4*)(W + (kt * 32 + kr) * HD + c4 * 4);
            *(float4*)&Ws[kr][c4 * 4] = v;
        }
        __syncthreads();

#pragma unroll
        for (int kk = 0; kk < 32; ++kk) {
            float a[4];
#pragma unroll
            for (int i = 0; i < 4; i++) a[i] = As[kk][ty * 4 + i];
            float w[8];
            *(float4*)&w[0] = *(const float4*)&Ws[kk][tx * 8];
            *(float4*)&w[4] = *(const float4*)&Ws[kk][tx * 8 + 4];
#pragma unroll
            for (int i = 0; i < 4; i++)
#pragma unroll
                for (int j = 0; j < 8; j++)
                    acc[i][j] = fmaf(a[i], w[j], acc[i][j]);
        }
        __syncthreads();
    }

    // Epilogue
    const int colbase = tx * 8;
    float bb[8], sc[8], bt2[8], mu[8];
#pragma unroll
    for (int j = 0; j < 8; j++) {
        int c = colbase + j;
        bb[j] = bias[c];
        if (DO_BN) {
            sc[j] = gam[c] * rsqrtf(mvar[c] + 1e-3f);
            bt2[j] = bet[c];
            mu[j] = mmean[c];
        }
    }
#pragma unroll
    for (int i = 0; i < 4; i++) {
        int r = row0 + ty * 4 + i;
        if (r >= M) break;
        float v[8];
#pragma unroll
        for (int j = 0; j < 8; j++) {
            float t = fmaxf(acc[i][j] + bb[j], 0.f);
            if (DO_BN) t = (t - mu[j]) * sc[j] + bt2[j];
            v[j] = t;
        }
        float4* o = (float4*)(out + (size_t)r * HD + colbase);
        o[0] = *(float4*)&v[0];
        o[1] = *(float4*)&v[4];
        if (DUAL) {
            float4* o2 = (float4*)(out2 + (size_t)r * HD + colbase);
            o2[0] = *(float4*)&v[0];
            o2[1] = *(float4*)&v[4];
        }
    }
}

// ---------------------------------------------------------------------------
// Edge scatter-add: out[dst,:] += h[src,:]. One warp per edge; each lane does
// one float4 gather + 4 atomic adds. h (25.6 MB) is L2-resident.
// ---------------------------------------------------------------------------
__global__ void scatter_add(const float* __restrict__ h,
                            const int* __restrict__ ei,
                            float* __restrict__ out)
{
    int t = blockIdx.x * blockDim.x + threadIdx.x;
    if (t >= EE * 32) return;
    int e = t >> 5;
    int j = t & 31;
    int src = ei[2 * e];
    int dst = ei[2 * e + 1];
    float4 v = *(const float4*)(h + (size_t)src * HD + j * 4);
    float* o = out + (size_t)dst * HD + j * 4;
    atomicAdd(o + 0, v.x);
    atomicAdd(o + 1, v.y);
    atomicAdd(o + 2, v.z);
    atomicAdd(o + 3, v.w);
}

// ---------------------------------------------------------------------------
// Final graph readout: out[batch[n],:] += h[n,:]
// ---------------------------------------------------------------------------
__global__ void seg_sum(const float* __restrict__ h,
                        const int* __restrict__ batch,
                        float* __restrict__ out)
{
    int t = blockIdx.x * blockDim.x + threadIdx.x;
    if (t >= NN * 32) return;
    int n = t >> 5;
    int j = t & 31;
    int b = batch[n];
    float4 v = *(const float4*)(h + (size_t)n * HD + j * 4);
    float* o = out + (size_t)b * HD + j * 4;
    atomicAdd(o + 0, v.x);
    atomicAdd(o + 1, v.y);
    atomicAdd(o + 2, v.z);
    atomicAdd(o + 3, v.w);
}

__global__ void zero_out(float* __restrict__ out, int n)
{
    int t = blockIdx.x * blockDim.x + threadIdx.x;
    if (t < n) out[t] = 0.f;
}

extern "C" void kernel_launch(void* const* d_in, const int* in_sizes, int n_in,
                              void* d_out, int out_size)
{
    const float* x   = (const float*)d_in[0];
    const int*   ei  = (const int*)d_in[1];
    const int*   bat = (const int*)d_in[2];
    const float* W1  = (const float*)d_in[3];
    const float* b1  = (const float*)d_in[4];
    const float* g1  = (const float*)d_in[5];
    const float* be1 = (const float*)d_in[6];
    const float* mm1 = (const float*)d_in[7];
    const float* mv1 = (const float*)d_in[8];
    const float* W2  = (const float*)d_in[9];
    const float* b2  = (const float*)d_in[10];
    const float* W3  = (const float*)d_in[11];
    const float* b3  = (const float*)d_in[12];
    const float* g2  = (const float*)d_in[13];
    const float* be2 = (const float*)d_in[14];
    const float* mm2 = (const float*)d_in[15];
    const float* mv2 = (const float*)d_in[16];
    const float* W4  = (const float*)d_in[17];
    const float* b4  = (const float*)d_in[18];
    float* out = (float*)d_out;

    float *bufA, *bufB, *bufC;
    cudaGetSymbolAddress((void**)&bufA, g_bufA);
    cudaGetSymbolAddress((void**)&bufB, g_bufB);
    cudaGetSymbolAddress((void**)&bufC, g_bufC);

    const int gemm_blocks = (NN + 63) / 64;           // 782
    const int scat_blocks = (EE * 32 + 255) / 256;    // 80000
    const int seg_blocks  = (NN * 32 + 255) / 256;

    // h = bn1(relu(x@W1+b1))
    gemm128<true, false><<<gemm_blocks, 256>>>(x, W1, b1, g1, be1, mm1, mv1,
                                               bufA, nullptr, NN);
    // h = relu(h@W2+b2); bufB = h, bufC = h (agg accumulator init)
    gemm128<false, true><<<gemm_blocks, 256>>>(bufA, W2, b2, nullptr, nullptr,
                                               nullptr, nullptr, bufB, bufC, NN);
    // bufC = h + segment_sum(h[src] -> dst)
    scatter_add<<<scat_blocks, 256>>>(bufB, ei, bufC);
    // h = bn2(relu(bufC@W3+b3)); bufA = h, bufB = h (agg accumulator init)
    gemm128<true, true><<<gemm_blocks, 256>>>(bufC, W3, b3, g2, be2, mm2, mv2,
                                              bufA, bufB, NN);
    // bufB = h + segment_sum(h[src] -> dst)
    scatter_add<<<scat_blocks, 256>>>(bufA, ei, bufB);
    // h = relu(bufB@W4+b4)
    gemm128<false, false><<<gemm_blocks, 256>>>(bufB, W4, b4, nullptr, nullptr,
                                                nullptr, nullptr, bufA, nullptr, NN);
    // out = segment_sum(h, batch)
    zero_out<<<(GG * HD + 255) / 256, 256>>>(out, GG * HD);
    seg_sum<<<seg_blocks, 256>>>(bufA, bat, out);
}

// round 2
// speedup vs baseline: 2.0795x; 2.0795x over previous
#include <cuda_runtime.h>

#define NN 50000
#define HD 128
#define EE 640000
#define GG 128

typedef unsigned long long ull;

// Scratch ping-pong buffers (25.6 MB each)
__device__ float g_bufA[NN * HD];
__device__ float g_bufB[NN * HD];
__device__ float g_bufC[NN * HD];

// ---------------------------------------------------------------------------
// Packed f32x2 helpers (Blackwell FFMA2 path)
// ---------------------------------------------------------------------------
__device__ __forceinline__ ull pack2(float lo, float hi) {
    ull r;
    asm("mov.b64 %0, {%1, %2};" : "=l"(r) : "f"(lo), "f"(hi));
    return r;
}
__device__ __forceinline__ void unpack2(ull v, float& lo, float& hi) {
    asm("mov.b64 {%0, %1}, %2;" : "=f"(lo), "=f"(hi) : "l"(v));
}
__device__ __forceinline__ ull fma2(ull a, ull b, ull c) {
    ull d;
    asm("fma.rn.f32x2 %0, %1, %2, %3;" : "=l"(d) : "l"(a), "l"(b), "l"(c));
    return d;
}

// ---------------------------------------------------------------------------
// GEMM: out[M,128] = epi(A[M,128] @ W[128,128] + bias)
// epi = relu, then optional BN. Optional dual write (out2 = same values, used
// to pre-init the aggregation accumulator, saving a copy pass).
// Tile: 128 rows x 128 cols per 256-thread block; thread tile 8x8; BK=32.
// Inner product uses packed fma.rn.f32x2 (2 MACs per issued instruction).
// ---------------------------------------------------------------------------
template <bool DO_BN, bool DUAL>
__global__ void __launch_bounds__(256, 2) gemm128(
    const float* __restrict__ A, const float* __restrict__ W,
    const float* __restrict__ bias,
    const float* __restrict__ gam, const float* __restrict__ bet,
    const float* __restrict__ mmean, const float* __restrict__ mvar,
    float* __restrict__ out, float* __restrict__ out2, int M)
{
    __shared__ float As[32][132];   // [k][row], 528B row stride (16B aligned)
    __shared__ float Ws[32][128];   // [k][col]

    const int tid = threadIdx.x;
    const int tx = tid & 15;        // col group (8 cols each)
    const int ty = tid >> 4;        // row group (8 rows each)
    const int row0 = blockIdx.x * 128;

    ull acc[8][4];                  // 8 rows x 4 col-pairs (f32x2)
#pragma unroll
    for (int i = 0; i < 8; i++)
#pragma unroll
        for (int j = 0; j < 4; j++) acc[i][j] = 0ull;

#pragma unroll 1
    for (int kt = 0; kt < 4; ++kt) {
        // Load A tile: 128 rows x 32 k (4 float4 per thread, coalesced),
        // stored transposed into As[k][row].
#pragma unroll
        for (int i = 0; i < 4; i++) {
            int idx = tid + i * 256;        // 0..1023 float4 slots
            int r = idx >> 3;               // 0..127
            int kq = idx & 7;               // float4 within 32-k chunk
            int grow = row0 + r;
            float4 v = make_float4(0.f, 0.f, 0.f, 0.f);
            if (grow < M)
                v = *(const float4*)(A + (size_t)grow * HD + kt * 32 + kq * 4);
            As[kq * 4 + 0][r] = v.x;
            As[kq * 4 + 1][r] = v.y;
            As[kq * 4 + 2][r] = v.z;
            As[kq * 4 + 3][r] = v.w;
        }
        // Load W tile: 32 k x 128 cols (4 float4 per thread, coalesced)
#pragma unroll
        for (int i = 0; i < 4; i++) {
            int idx = tid + i * 256;
            int kr = idx >> 5;              // 0..31
            int c4 = idx & 31;
            *(float4*)&Ws[kr][c4 * 4] =
                *(const float4*)(W + (size_t)(kt * 32 + kr) * HD + c4 * 4);
        }
        __syncthreads();

#pragma unroll
        for (int kk = 0; kk < 32; ++kk) {
            float4 alo = *(const float4*)&As[kk][ty * 8];
            float4 ahi = *(const float4*)&As[kk][ty * 8 + 4];
            union { float4 f; ull u[2]; } wl, wh;
            wl.f = *(const float4*)&Ws[kk][tx * 8];
            wh.f = *(const float4*)&Ws[kk][tx * 8 + 4];
            ull w2[4] = { wl.u[0], wl.u[1], wh.u[0], wh.u[1] };
            float a[8] = { alo.x, alo.y, alo.z, alo.w,
                           ahi.x, ahi.y, ahi.z, ahi.w };
#pragma unroll
            for (int i = 0; i < 8; i++) {
                ull a2 = pack2(a[i], a[i]);
#pragma unroll
                for (int j = 0; j < 4; j++)
                    acc[i][j] = fma2(a2, w2[j], acc[i][j]);
            }
        }
        __syncthreads();
    }

    // Epilogue
    const int colbase = tx * 8;
    float bb[8], sc[8], bt2[8], mu[8];
#pragma unroll
    for (int j = 0; j < 8; j++) {
        int c = colbase + j;
        bb[j] = bias[c];
        if (DO_BN) {
            sc[j] = gam[c] * rsqrtf(mvar[c] + 1e-3f);
            bt2[j] = bet[c];
            mu[j] = mmean[c];
        }
    }
#pragma unroll
    for (int i = 0; i < 8; i++) {
        int r = row0 + ty * 8 + i;
        if (r >= M) break;
        float v[8];
#pragma unroll
        for (int j = 0; j < 4; j++)
            unpack2(acc[i][j], v[2 * j], v[2 * j + 1]);
#pragma unroll
        for (int j = 0; j < 8; j++) {
            float t = fmaxf(v[j] + bb[j], 0.f);
            if (DO_BN) t = (t - mu[j]) * sc[j] + bt2[j];
            v[j] = t;
        }
        float4* o = (float4*)(out + (size_t)r * HD + colbase);
        o[0] = *(float4*)&v[0];
        o[1] = *(float4*)&v[4];
        if (DUAL) {
            float4* o2 = (float4*)(out2 + (size_t)r * HD + colbase);
            o2[0] = *(float4*)&v[0];
            o2[1] = *(float4*)&v[4];
        }
    }
}

// ---------------------------------------------------------------------------
// Edge scatter-add: out[dst,:] += h[src,:]. One warp per edge; each lane does
// one float4 gather + ONE vector atomic (red.global.add.v4.f32, sm_90+).
// h (25.6 MB) is L2-resident.
// ---------------------------------------------------------------------------
__global__ void scatter_add(const float* __restrict__ h,
                            const int* __restrict__ ei,
                            float* __restrict__ out)
{
    int t = blockIdx.x * blockDim.x + threadIdx.x;
    if (t >= EE * 32) return;
    int e = t >> 5;
    int j = t & 31;
    int src = __ldg(ei + 2 * e);
    int dst = __ldg(ei + 2 * e + 1);
    float4 v = __ldg((const float4*)(h + (size_t)src * HD) + j);
    float4* o = (float4*)(out + (size_t)dst * HD) + j;
    asm volatile("red.global.add.v4.f32 [%0], {%1, %2, %3, %4};"
                 :: "l"(o), "f"(v.x), "f"(v.y), "f"(v.z), "f"(v.w)
                 : "memory");
}

// ---------------------------------------------------------------------------
// Final graph readout: out[batch[n],:] += h[n,:]. batch is sorted, so a block
// accumulates a contiguous node chunk in registers and flushes one atomic per
// group boundary (atomic count ~200K instead of 6.4M).
// ---------------------------------------------------------------------------
#define SEG_CH 64
__global__ void seg_sum(const float* __restrict__ h,
                        const int* __restrict__ batch,
                        float* __restrict__ out)
{
    int n0 = blockIdx.x * SEG_CH;
    if (n0 >= NN) return;
    int j = threadIdx.x;            // 0..127: one column per thread
    int nend = n0 + SEG_CH;
    if (nend > NN) nend = NN;
    float acc = 0.f;
    int cur = __ldg(batch + n0);
    for (int n = n0; n < nend; ++n) {
        int b = __ldg(batch + n);
        if (b != cur) {
            atomicAdd(out + (size_t)cur * HD + j, acc);
            acc = 0.f;
            cur = b;
        }
        acc += __ldg(h + (size_t)n * HD + j);
    }
    atomicAdd(out + (size_t)cur * HD + j, acc);
}

__global__ void zero_out(float* __restrict__ out, int n)
{
    int t = blockIdx.x * blockDim.x + threadIdx.x;
    if (t < n) out[t] = 0.f;
}

extern "C" void kernel_launch(void* const* d_in, const int* in_sizes, int n_in,
                              void* d_out, int out_size)
{
    const float* x   = (const float*)d_in[0];
    const int*   ei  = (const int*)d_in[1];
    const int*   bat = (const int*)d_in[2];
    const float* W1  = (const float*)d_in[3];
    const float* b1  = (const float*)d_in[4];
    const float* g1  = (const float*)d_in[5];
    const float* be1 = (const float*)d_in[6];
    const float* mm1 = (const float*)d_in[7];
    const float* mv1 = (const float*)d_in[8];
    const float* W2  = (const float*)d_in[9];
    const float* b2  = (const float*)d_in[10];
    const float* W3  = (const float*)d_in[11];
    const float* b3  = (const float*)d_in[12];
    const float* g2  = (const float*)d_in[13];
    const float* be2 = (const float*)d_in[14];
    const float* mm2 = (const float*)d_in[15];
    const float* mv2 = (const float*)d_in[16];
    const float* W4  = (const float*)d_in[17];
    const float* b4  = (const float*)d_in[18];
    float* out = (float*)d_out;

    float *bufA, *bufB, *bufC;
    cudaGetSymbolAddress((void**)&bufA, g_bufA);
    cudaGetSymbolAddress((void**)&bufB, g_bufB);
    cudaGetSymbolAddress((void**)&bufC, g_bufC);

    const int gemm_blocks = (NN + 127) / 128;         // 391
    const int scat_blocks = (EE * 32 + 255) / 256;    // 80000
    const int seg_blocks  = (NN + SEG_CH - 1) / SEG_CH;

    // h = bn1(relu(x@W1+b1))
    gemm128<true, false><<<gemm_blocks, 256>>>(x, W1, b1, g1, be1, mm1, mv1,
                                               bufA, nullptr, NN);
    // h = relu(h@W2+b2); bufB = h, bufC = h (agg accumulator init)
    gemm128<false, true><<<gemm_blocks, 256>>>(bufA, W2, b2, nullptr, nullptr,
                                               nullptr, nullptr, bufB, bufC, NN);
    // bufC = h + segment_sum(h[src] -> dst)
    scatter_add<<<scat_blocks, 256>>>(bufB, ei, bufC);
    // h = bn2(relu(bufC@W3+b3)); bufA = h, bufB = h (agg accumulator init)
    gemm128<true, true><<<gemm_blocks, 256>>>(bufC, W3, b3, g2, be2, mm2, mv2,
                                              bufA, bufB, NN);
    // bufB = h + segment_sum(h[src] -> dst)
    scatter_add<<<scat_blocks, 256>>>(bufA, ei, bufB);
    // h = relu(bufB@W4+b4)
    gemm128<false, false><<<gemm_blocks, 256>>>(bufB, W4, b4, nullptr, nullptr,
                                                nullptr, nullptr, bufA, nullptr, NN);
    // out = segment_sum(h, batch)
    zero_out<<<(GG * HD + 255) / 256, 256>>>(out, GG * HD);
    seg_sum<<<seg_blocks, 128>>>(bufA, bat, out);
}